// round 1
// baseline (speedup 1.0000x reference)
#include <cuda_runtime.h>
#include <cuda_bf16.h>
#include <cstdint>

// Problem constants (fixed by the reference).
#define OUTF 4096
#define INF  4096
#define NBATCH 4096

// 64 MB dense scratch for the scattered weight matrix.
// __device__ global: allowed (no runtime allocation).
__device__ float g_W[(size_t)OUTF * INF];

// ---------------------------------------------------------------------------
// Kernel 1: zero the dense W (vectorized grid-stride memset).
// ---------------------------------------------------------------------------
__global__ void zero_W_kernel() {
    size_t n4 = (size_t)OUTF * INF / 4;
    float4* p = reinterpret_cast<float4*>(g_W);
    float4 z = make_float4(0.f, 0.f, 0.f, 0.f);
    for (size_t i = (size_t)blockIdx.x * blockDim.x + threadIdx.x; i < n4;
         i += (size_t)gridDim.x * blockDim.x)
        p[i] = z;
}

// ---------------------------------------------------------------------------
// Kernel 2: scatter-add COO values into dense W (duplicates sum -> atomicAdd).
// ---------------------------------------------------------------------------
__global__ void scatter_W_kernel(const float* __restrict__ w,
                                 const int* __restrict__ rows,
                                 const int* __restrict__ cols,
                                 int nnz) {
    int i = blockIdx.x * blockDim.x + threadIdx.x;
    int stride = gridDim.x * blockDim.x;
    for (; i < nnz; i += stride) {
        int r = rows[i];
        int c = cols[i];
        atomicAdd(&g_W[(size_t)r * INF + c], w[i]);
    }
}

// ---------------------------------------------------------------------------
// Kernel 3: Y[b][o] = sum_k X[b][k] * W[o][k] + bias[o]
// Both operands K-contiguous (an "NT" gemm): classic register-tiled SGEMM.
// CTA tile 128x128, K-tile 16, 256 threads, 8x8 accumulators per thread.
// ---------------------------------------------------------------------------
#define BM 128
#define BN 128
#define BK 16
#define TM 8
#define TN 8

__global__ __launch_bounds__(256, 2)
void sgemm_nt_bias(const float* __restrict__ X,
                   const float* __restrict__ bias,
                   float* __restrict__ Y) {
    __shared__ float As[BK][BM];
    __shared__ float Bs[BK][BN];

    const float* __restrict__ W = g_W;

    const int tid = threadIdx.x;
    const int tn  = tid & 15;   // 0..15, column group
    const int tm  = tid >> 4;   // 0..15, row group
    const int bm  = blockIdx.y * BM;
    const int bn  = blockIdx.x * BN;

    float acc[TM][TN] = {};

    // Each thread loads 2 float4 from X-tile and 2 from W-tile per K-step.
    // Flat float4 index: idx = tid + l*256; tile row = idx>>2 (0..127),
    // k-quad = (idx&3)*4 (0..12).
    float4 pa[2], pb[2];
#pragma unroll
    for (int l = 0; l < 2; l++) {
        int idx = tid + l * 256;
        int row = idx >> 2;
        int kc  = (idx & 3) << 2;
        pa[l] = *reinterpret_cast<const float4*>(&X[(size_t)(bm + row) * INF + kc]);
        pb[l] = *reinterpret_cast<const float4*>(&W[(size_t)(bn + row) * INF + kc]);
    }

    for (int k0 = 0; k0 < INF; k0 += BK) {
        // Commit prefetched tile to shared (transposed to [k][mn]).
#pragma unroll
        for (int l = 0; l < 2; l++) {
            int idx = tid + l * 256;
            int row = idx >> 2;
            int kc  = (idx & 3) << 2;
            As[kc + 0][row] = pa[l].x;
            As[kc + 1][row] = pa[l].y;
            As[kc + 2][row] = pa[l].z;
            As[kc + 3][row] = pa[l].w;
            Bs[kc + 0][row] = pb[l].x;
            Bs[kc + 1][row] = pb[l].y;
            Bs[kc + 2][row] = pb[l].z;
            Bs[kc + 3][row] = pb[l].w;
        }
        __syncthreads();

        // Prefetch next K-tile while computing on this one.
        const int k1 = k0 + BK;
        if (k1 < INF) {
#pragma unroll
            for (int l = 0; l < 2; l++) {
                int idx = tid + l * 256;
                int row = idx >> 2;
                int kc  = (idx & 3) << 2;
                pa[l] = *reinterpret_cast<const float4*>(
                    &X[(size_t)(bm + row) * INF + k1 + kc]);
                pb[l] = *reinterpret_cast<const float4*>(
                    &W[(size_t)(bn + row) * INF + k1 + kc]);
            }
        }

#pragma unroll
        for (int kk = 0; kk < BK; kk++) {
            float a[TM], b[TN];
#pragma unroll
            for (int i = 0; i < TM; i++) a[i] = As[kk][tm * TM + i];
#pragma unroll
            for (int j = 0; j < TN; j++) b[j] = Bs[kk][tn * TN + j];
#pragma unroll
            for (int i = 0; i < TM; i++)
#pragma unroll
                for (int j = 0; j < TN; j++)
                    acc[i][j] += a[i] * b[j];
        }
        __syncthreads();
    }

    // Epilogue: add bias, vectorized stores (row-major [BATCH, OUT]).
#pragma unroll
    for (int i = 0; i < TM; i++) {
        const int m = bm + tm * TM + i;
        float* yrow = &Y[(size_t)m * OUTF];
#pragma unroll
        for (int j = 0; j < TN; j += 4) {
            const int n = bn + tn * TN + j;
            float4 v;
            v.x = acc[i][j + 0] + bias[n + 0];
            v.y = acc[i][j + 1] + bias[n + 1];
            v.z = acc[i][j + 2] + bias[n + 2];
            v.w = acc[i][j + 3] + bias[n + 3];
            *reinterpret_cast<float4*>(&yrow[n]) = v;
        }
    }
}

// ---------------------------------------------------------------------------
// Launch: zero -> scatter -> gemm (stream-ordered, graph-capturable,
// allocation-free).
// Input order (metadata): x, w_values, bias, rows, cols. Output: float32.
// ---------------------------------------------------------------------------
extern "C" void kernel_launch(void* const* d_in, const int* in_sizes, int n_in,
                              void* d_out, int out_size) {
    const float* x     = (const float*)d_in[0];
    const float* wvals = (const float*)d_in[1];
    const float* bias  = (const float*)d_in[2];
    const int*   rows  = (const int*)d_in[3];
    const int*   cols  = (const int*)d_in[4];
    float*       out   = (float*)d_out;
    const int    nnz   = in_sizes[1];

    zero_W_kernel<<<2048, 256>>>();
    scatter_W_kernel<<<(nnz + 255) / 256, 256>>>(wvals, rows, cols, nnz);

    dim3 grid(OUTF / BN, NBATCH / BM);
    sgemm_nt_bias<<<grid, 256>>>(x, bias, out);
}

// round 5
// speedup vs baseline: 2.4019x; 2.4019x over previous
#include <cuda_runtime.h>
#include <cuda_bf16.h>
#include <cstdint>

// ---------------------------------------------------------------------------
// Problem constants
// ---------------------------------------------------------------------------
#define OUTF   4096
#define INF    4096
#define NBATCH 4096

// Device-global scratch (allocation-guard safe).
__device__ float         g_W [(size_t)OUTF  * INF];   // 64 MB scattered dense weights
__device__ __nv_bfloat16 g_Ah[(size_t)NBATCH * INF];  // 32 MB X hi
__device__ __nv_bfloat16 g_Al[(size_t)NBATCH * INF];  // 32 MB X lo
__device__ __nv_bfloat16 g_Bh[(size_t)OUTF  * INF];   // 32 MB W hi
__device__ __nv_bfloat16 g_Bl[(size_t)OUTF  * INF];   // 32 MB W lo

// ---------------------------------------------------------------------------
// PTX helpers (sm_80-level features only: cp.async, ldmatrix, mma.sync)
// ---------------------------------------------------------------------------
__device__ __forceinline__ uint32_t smem_u32(const void* p) {
    uint32_t a;
    asm("{ .reg .u64 t; cvta.to.shared.u64 t, %1; cvt.u32.u64 %0, t; }"
        : "=r"(a) : "l"(p));
    return a;
}

__device__ __forceinline__ void cpa16(uint32_t dst, const void* src) {
    asm volatile("cp.async.cg.shared.global [%0], [%1], 16;"
                 :: "r"(dst), "l"(__cvta_generic_to_global(src)));
}
#define CP_COMMIT() asm volatile("cp.async.commit_group;" ::: "memory")
#define CP_WAIT1()  asm volatile("cp.async.wait_group 1;" ::: "memory")

__device__ __forceinline__ void ldsm4(uint32_t* r, uint32_t addr) {
    asm volatile("ldmatrix.sync.aligned.m8n8.x4.shared.b16 {%0,%1,%2,%3}, [%4];"
                 : "=r"(r[0]), "=r"(r[1]), "=r"(r[2]), "=r"(r[3]) : "r"(addr));
}

__device__ __forceinline__ void mma16816(float* d, const uint32_t* a,
                                         const uint32_t* b) {
    asm volatile(
        "mma.sync.aligned.m16n8k16.row.col.f32.bf16.bf16.f32 "
        "{%0,%1,%2,%3}, {%4,%5,%6,%7}, {%8,%9}, {%0,%1,%2,%3};"
        : "+f"(d[0]), "+f"(d[1]), "+f"(d[2]), "+f"(d[3])
        : "r"(a[0]), "r"(a[1]), "r"(a[2]), "r"(a[3]), "r"(b[0]), "r"(b[1]));
}

// ---------------------------------------------------------------------------
// Pre-kernels: zero W, scatter COO, hi/lo bf16 split of X and W
// ---------------------------------------------------------------------------
__global__ void zero_W_kernel() {
    size_t n4 = (size_t)OUTF * INF / 4;
    float4* p = reinterpret_cast<float4*>(g_W);
    float4 z = make_float4(0.f, 0.f, 0.f, 0.f);
    for (size_t i = (size_t)blockIdx.x * blockDim.x + threadIdx.x; i < n4;
         i += (size_t)gridDim.x * blockDim.x)
        p[i] = z;
}

__global__ void scatter_W_kernel(const float* __restrict__ w,
                                 const int* __restrict__ rows,
                                 const int* __restrict__ cols, int nnz) {
    int i = blockIdx.x * blockDim.x + threadIdx.x;
    int stride = gridDim.x * blockDim.x;
    for (; i < nnz; i += stride)
        atomicAdd(&g_W[(size_t)rows[i] * INF + cols[i]], w[i]);
}

__device__ __forceinline__ void split_body(const float* __restrict__ src,
                                           __nv_bfloat16* __restrict__ dh,
                                           __nv_bfloat16* __restrict__ dl) {
    size_t n4 = (size_t)INF * NBATCH / 4;
    for (size_t i = (size_t)blockIdx.x * blockDim.x + threadIdx.x; i < n4;
         i += (size_t)gridDim.x * blockDim.x) {
        float4 v = reinterpret_cast<const float4*>(src)[i];
        __nv_bfloat16 h0 = __float2bfloat16_rn(v.x);
        __nv_bfloat16 h1 = __float2bfloat16_rn(v.y);
        __nv_bfloat16 h2 = __float2bfloat16_rn(v.z);
        __nv_bfloat16 h3 = __float2bfloat16_rn(v.w);
        __nv_bfloat16 l0 = __float2bfloat16_rn(v.x - __bfloat162float(h0));
        __nv_bfloat16 l1 = __float2bfloat16_rn(v.y - __bfloat162float(h1));
        __nv_bfloat16 l2 = __float2bfloat16_rn(v.z - __bfloat162float(h2));
        __nv_bfloat16 l3 = __float2bfloat16_rn(v.w - __bfloat162float(h3));
        reinterpret_cast<__nv_bfloat162*>(dh)[i * 2 + 0] = __halves2bfloat162(h0, h1);
        reinterpret_cast<__nv_bfloat162*>(dh)[i * 2 + 1] = __halves2bfloat162(h2, h3);
        reinterpret_cast<__nv_bfloat162*>(dl)[i * 2 + 0] = __halves2bfloat162(l0, l1);
        reinterpret_cast<__nv_bfloat162*>(dl)[i * 2 + 1] = __halves2bfloat162(l2, l3);
    }
}
__global__ void split_x_kernel(const float* __restrict__ x) { split_body(x, g_Ah, g_Al); }
__global__ void split_w_kernel() { split_body(g_W, g_Bh, g_Bl); }

// ---------------------------------------------------------------------------
// bf16x3 HMMA GEMM: Y = X.W^T + bias
// CTA 128x128, BK=32, 3-stage cp.async pipeline, 8 warps (4x2), warp 32x64.
// ---------------------------------------------------------------------------
#define BM 128
#define BN 128
#define BK 32
#define NIT (INF / BK)          // 128
#define NSTAGE 3
#define ROWB 80                 // 64B of data + 16B pad: conflict-free ldmatrix
#define TILEB (128 * ROWB)      // 10240 B
#define STAGEB (4 * TILEB)      // Ah | Al | Bh | Bl
#define SMEMB (NSTAGE * STAGEB) // 122880 B

__device__ __forceinline__ void load_stage(uint32_t sb, int stage, int kblk,
                                           int bm, int bn, int tid) {
    const uint32_t base = sb + stage * STAGEB;
    const int k0 = kblk * BK;
#pragma unroll
    for (int j = 0; j < 2; j++) {
        int idx = tid + j * 256;
        int r   = idx >> 2;          // 0..127
        int ce  = (idx & 3) * 8;     // element col
        int cb  = (idx & 3) * 16;    // byte col
        uint32_t drow = base + r * ROWB + cb;
        const size_t arow = (size_t)(bm + r) * INF + k0 + ce;
        const size_t brow = (size_t)(bn + r) * INF + k0 + ce;
        cpa16(drow,             g_Ah + arow);
        cpa16(drow + TILEB,     g_Al + arow);
        cpa16(drow + 2 * TILEB, g_Bh + brow);
        cpa16(drow + 3 * TILEB, g_Bl + brow);
    }
}

__global__ __launch_bounds__(256, 1)
void gemm_bf16x3(const float* __restrict__ bias, float* __restrict__ Y) {
    extern __shared__ char smem[];
    const uint32_t sb = smem_u32(smem);

    const int tid  = threadIdx.x;
    const int lane = tid & 31;
    const int wid  = tid >> 5;
    const int wm   = wid & 3;        // 0..3 -> 32-row slab
    const int wn   = wid >> 2;       // 0..1 -> 64-col slab
    const int bm   = blockIdx.y * BM;
    const int bn   = blockIdx.x * BN;

    // ldmatrix per-lane address offsets (within a tile)
    const uint32_t aRow = (uint32_t)(wm * 32 + (lane & 15)) * ROWB + ((lane >> 4) << 4);
    const uint32_t bRow = (uint32_t)(wn * 64 + ((lane >> 4) << 3) + (lane & 7)) * ROWB
                        + (((lane >> 3) & 1) << 4);

    float acc[2][8][4] = {};

    load_stage(sb, 0, 0, bm, bn, tid); CP_COMMIT();
    load_stage(sb, 1, 1, bm, bn, tid); CP_COMMIT();

#pragma unroll 1
    for (int it = 0; it < NIT; it++) {
        CP_WAIT1();
        __syncthreads();
        const int ld = it + 2;
        if (ld < NIT) load_stage(sb, ld % NSTAGE, ld, bm, bn, tid);
        CP_COMMIT();

        const uint32_t base = sb + (it % NSTAGE) * STAGEB;
#pragma unroll
        for (int ks = 0; ks < 2; ks++) {
            const uint32_t kb = ks * 32;   // 16 elements = 32 bytes
            uint32_t aH[2][4], aL[2][4], bH[4][4], bL[4][4];
#pragma unroll
            for (int mt = 0; mt < 2; mt++) {
                ldsm4(aH[mt], base + aRow + mt * 16 * ROWB + kb);
                ldsm4(aL[mt], base + TILEB + aRow + mt * 16 * ROWB + kb);
            }
#pragma unroll
            for (int nt2 = 0; nt2 < 4; nt2++) {
                // B stored [n][k] row-major (K contiguous) -> NON-trans ldmatrix
                // yields the .col B fragment directly.
                ldsm4(bH[nt2], base + 2 * TILEB + bRow + nt2 * 16 * ROWB + kb);
                ldsm4(bL[nt2], base + 3 * TILEB + bRow + nt2 * 16 * ROWB + kb);
            }
#pragma unroll
            for (int mt = 0; mt < 2; mt++)
#pragma unroll
                for (int nt = 0; nt < 8; nt++) {
                    const uint32_t* bh = &bH[nt >> 1][(nt & 1) * 2];
                    const uint32_t* bl = &bL[nt >> 1][(nt & 1) * 2];
                    mma16816(acc[mt][nt], aH[mt], bh);
                    mma16816(acc[mt][nt], aH[mt], bl);
                    mma16816(acc[mt][nt], aL[mt], bh);
                }
        }
    }

    // Epilogue: bias + store. acc tile (mt,nt): rows lane>>2 (+8), cols (lane&3)*2.
#pragma unroll
    for (int mt = 0; mt < 2; mt++) {
        const int r0 = bm + wm * 32 + mt * 16 + (lane >> 2);
#pragma unroll
        for (int nt = 0; nt < 8; nt++) {
            const int c = bn + wn * 64 + nt * 8 + (lane & 3) * 2;
            const float2 bv = *reinterpret_cast<const float2*>(&bias[c]);
            float2 v0, v1;
            v0.x = acc[mt][nt][0] + bv.x;
            v0.y = acc[mt][nt][1] + bv.y;
            v1.x = acc[mt][nt][2] + bv.x;
            v1.y = acc[mt][nt][3] + bv.y;
            *reinterpret_cast<float2*>(&Y[(size_t)r0 * OUTF + c])       = v0;
            *reinterpret_cast<float2*>(&Y[(size_t)(r0 + 8) * OUTF + c]) = v1;
        }
    }
}

// ---------------------------------------------------------------------------
// Launch
// ---------------------------------------------------------------------------
extern "C" void kernel_launch(void* const* d_in, const int* in_sizes, int n_in,
                              void* d_out, int out_size) {
    const float* x     = (const float*)d_in[0];
    const float* wvals = (const float*)d_in[1];
    const float* bias  = (const float*)d_in[2];
    const int*   rows  = (const int*)d_in[3];
    const int*   cols  = (const int*)d_in[4];
    float*       out   = (float*)d_out;
    const int    nnz   = in_sizes[1];

    cudaFuncSetAttribute(gemm_bf16x3, cudaFuncAttributeMaxDynamicSharedMemorySize,
                         SMEMB);

    zero_W_kernel<<<2048, 256>>>();
    scatter_W_kernel<<<(nnz + 255) / 256, 256>>>(wvals, rows, cols, nnz);
    split_x_kernel<<<4096, 256>>>(x);
    split_w_kernel<<<4096, 256>>>();

    dim3 grid(OUTF / BN, NBATCH / BM);   // (32, 32)
    gemm_bf16x3<<<grid, 256, SMEMB>>>(bias, out);
}